// round 12
// baseline (speedup 1.0000x reference)
#include <cuda_runtime.h>
#include <math.h>

// Problem constants
#define BB   16
#define CI   64
#define CO   64
#define SS   256
#define MM1  32
#define MM2  32
#define NR   63            // 2*m1-1 fx modes (fx = r-31)
#define NMODE (NR*MM2)     // 2016
#define NBI  (BB*CI)       // 1024
#define NBO  (BB*CO)       // 1024
#define KKC  64            // 2*MM2 interleaved re/im columns

typedef unsigned long long u64t;

// ---- packed f32x2 helpers (FFMA2 path, Blackwell-only via PTX) ----
__device__ __forceinline__ u64t pk(float lo, float hi) {
    u64t r;
    asm("mov.b64 %0, {%1, %2};" : "=l"(r)
        : "r"(__float_as_uint(lo)), "r"(__float_as_uint(hi)));
    return r;
}
__device__ __forceinline__ u64t pk2(float v) { return pk(v, v); }
__device__ __forceinline__ float2 upk(u64t v) {
    unsigned lo, hi;
    asm("mov.b64 {%0, %1}, %2;" : "=r"(lo), "=r"(hi) : "l"(v));
    return make_float2(__uint_as_float(lo), __uint_as_float(hi));
}
__device__ __forceinline__ void fma2(u64t& d, u64t a, u64t b) {
    asm("fma.rn.f32x2 %0, %1, %2, %3;" : "=l"(d) : "l"(a), "l"(b), "l"(d));
}

// -------- device scratch --------
__device__ __align__(16) float g_tab[512];                    // cos[0..255], sin[256..511]
__device__ __align__(16) u64t  g_cc[256];                     // {c,c}
__device__ __align__(16) u64t  g_ss[256];                     // {s,s}
__device__ __align__(16) u64t  g_nsps[256];                   // {-s,s}
__device__ __align__(16) float g_TP[(size_t)NBI * SS * KKC];  // stage1 out T, reused as stage4 out P
__device__ __align__(16) float g_M1[(size_t)NBI * NMODE * 2]; // [bi][mode][2]
__device__ __align__(16) float g_W [(size_t)NMODE * CI * CO * 2]; // [mode][i*64+o][2] (scaled)
__device__ __align__(16) float g_M2[(size_t)NMODE * NBO * 2]; // [mode][b*64+o][2]

// ======================= K0: trig table =======================
__global__ void k_tab() {
    int n = threadIdx.x;
    double a = 2.0 * M_PI * (double)n / 256.0;
    float c = (float)cos(a), s = (float)sin(a);
    g_tab[n]       = c;
    g_tab[256 + n] = s;
    g_cc[n]   = pk2(c);
    g_ss[n]   = pk2(s);
    g_nsps[n] = pk(-s, s);
}

// ======================= K1: weight build + transpose =======================
__global__ void k_wbuild(const float* __restrict__ y0r, const float* __restrict__ y0i,
                         const float* __restrict__ ypr, const float* __restrict__ ypi,
                         const float* __restrict__ w00) {
    __shared__ float2 tile[32][33];
    int m0 = blockIdx.x * 32, io0 = blockIdx.y * 32;
    int tx = threadIdx.x, ty = threadIdx.y;   // 32 x 8
    #pragma unroll
    for (int q = 0; q < 4; q++) {
        int io = io0 + ty + 8 * q;
        int m  = m0 + tx;
        int r = m >> 5, k = m & 31;
        float wr, wi;
        if (k == 0) {
            if (r < 31)       { wr = y0r[io * 31 + r];        wi =  y0i[io * 31 + r]; }
            else if (r == 31) { wr = w00[io];                 wi =  0.f; }
            else              { wr = y0r[io * 31 + (62 - r)]; wi = -y0i[io * 31 + (62 - r)]; }
        } else {
            int idx = (io * 63 + r) * 31 + (k - 1);
            wr = ypr[idx]; wi = ypi[idx];
        }
        float sc = (k == 0 ? 1.0f : 2.0f) * (1.0f / 65536.0f);
        tile[ty + 8 * q][tx] = make_float2(wr * sc, wi * sc);
    }
    __syncthreads();
    #pragma unroll
    for (int q = 0; q < 4; q++) {
        int m  = m0 + ty + 8 * q;
        int io = io0 + tx;
        float2 w = tile[tx][ty + 8 * q];
        ((float2*)g_W)[(size_t)m * 4096 + io] = w;
    }
}

// ======================= K2: stage1 column DFT (GEMM 262144x64x256) — R3 proven =======================
__global__ void __launch_bounds__(256) k_s1(const float* __restrict__ x) {
    extern __shared__ float sm[];
    float* As = sm;                 // [32][257] transposed A tile
    float* Es = sm + 32 * 257;      // [256][64]
    for (int idx = threadIdx.x; idx < 256 * 64; idx += 256) {
        int v = idx >> 6, kk = idx & 63, ky = kk >> 1;
        int a = (ky * v) & 255;
        Es[idx] = (kk & 1) ? -g_tab[256 + a] : g_tab[a];
    }
    int row0 = blockIdx.x * 256;
    int i = threadIdx.x & 31, j = threadIdx.x >> 5;
    u64t acc2[8][4];
    #pragma unroll
    for (int t = 0; t < 8; t++)
        #pragma unroll
        for (int p = 0; p < 4; p++) acc2[t][p] = 0ULL;

    for (int k0 = 0; k0 < 256; k0 += 32) {
        __syncthreads();
        const float4* src = (const float4*)(x + (size_t)(row0 + threadIdx.x) * 256 + k0);
        #pragma unroll
        for (int q = 0; q < 8; q++) {
            float4 v4 = src[q];
            As[(q * 4 + 0) * 257 + threadIdx.x] = v4.x;
            As[(q * 4 + 1) * 257 + threadIdx.x] = v4.y;
            As[(q * 4 + 2) * 257 + threadIdx.x] = v4.z;
            As[(q * 4 + 3) * 257 + threadIdx.x] = v4.w;
        }
        __syncthreads();
        #pragma unroll 4
        for (int k = 0; k < 32; k++) {
            u64t a2[8], b2[4];
            #pragma unroll
            for (int t = 0; t < 8; t++) a2[t] = pk2(As[k * 257 + i + 32 * t]);
            #pragma unroll
            for (int p = 0; p < 4; p++)
                b2[p] = *(const u64t*)&Es[(k0 + k) * 64 + 2 * (j + 8 * p)];
            #pragma unroll
            for (int t = 0; t < 8; t++)
                #pragma unroll
                for (int p = 0; p < 4; p++) fma2(acc2[t][p], a2[t], b2[p]);
        }
    }
    __syncthreads();
    float* sC = sm;  // [256][65]
    #pragma unroll
    for (int t = 0; t < 8; t++)
        #pragma unroll
        for (int p = 0; p < 4; p++) {
            float2 up = upk(acc2[t][p]);
            int c = 2 * (j + 8 * p);
            sC[(i + 32 * t) * 65 + c]     = up.x;
            sC[(i + 32 * t) * 65 + c + 1] = up.y;
        }
    __syncthreads();
    for (int f = threadIdx.x; f < 256 * 16; f += 256) {
        int r = f >> 4, c4 = (f & 15) * 4;
        float4 v4 = make_float4(sC[r * 65 + c4], sC[r * 65 + c4 + 1],
                                sC[r * 65 + c4 + 2], sC[r * 65 + c4 + 3]);
        ((float4*)(g_TP + (size_t)(row0 + r) * 64))[f & 15] = v4;
    }
}

// ======================= K3: stage2 row DFT per image (R3 math, occupancy fix) =======================
// M1[bi][r*32+ky] = sum_u e^{-2pi i (r-31) u /256} * T[bi][u][ky]
// 256 threads: each does 2 fx values x 4 ky-pairs (8 u64 accumulators).
__global__ void __launch_bounds__(256) k_s2() {
    extern __shared__ float Ts[];        // [256][64] interleaved re/im (64KB)
    __shared__ u64t ccS[256], ssS[256];
    int bi = blockIdx.x;
    {
        int idx = threadIdx.x;
        if (idx < 256) { ccS[idx] = g_cc[idx]; ssS[idx] = g_ss[idx]; }
        const float4* src = (const float4*)(g_TP + (size_t)bi * SS * KKC);
        for (int f = threadIdx.x; f < 256 * 16; f += 256)
            ((float4*)Ts)[f] = src[f];
    }
    __syncthreads();
    int fxg = threadIdx.x & 15, kyg = (threadIdx.x >> 4) & 7, th = threadIdx.x >> 7;
    u64t acc2[2][4];   // {aR, aI}
    #pragma unroll
    for (int t = 0; t < 2; t++)
        #pragma unroll
        for (int s2 = 0; s2 < 4; s2++) acc2[t][s2] = 0ULL;

    #pragma unroll 2
    for (int u = 0; u < 256; u++) {
        u64t tv[4], tw[4], c2[2], s2v[2];
        #pragma unroll
        for (int s2 = 0; s2 < 4; s2++) {
            tv[s2] = *(const u64t*)&Ts[(u * 32 + kyg + 8 * s2) * 2];
            float2 f = upk(tv[s2]);
            tw[s2] = pk(f.y, -f.x);          // {ti, -tr}
        }
        #pragma unroll
        for (int t = 0; t < 2; t++) {
            int r = fxg + 16 * (2 * th + t);
            int idx = ((r - 31) * u) & 255;
            c2[t]  = ccS[idx];
            s2v[t] = ssS[idx];
        }
        #pragma unroll
        for (int t = 0; t < 2; t++)
            #pragma unroll
            for (int s2 = 0; s2 < 4; s2++) {
                fma2(acc2[t][s2], tv[s2], c2[t]);   // aR+=tr*c,  aI+=ti*c
                fma2(acc2[t][s2], tw[s2], s2v[t]);  // aR+=ti*sn, aI-=tr*sn
            }
    }
    float2* out = (float2*)(g_M1 + (size_t)bi * NMODE * 2);
    #pragma unroll
    for (int t = 0; t < 2; t++) {
        int r = fxg + 16 * (2 * th + t);
        if (r < 63) {
            #pragma unroll
            for (int s2 = 0; s2 < 4; s2++) {
                int ky = kyg + 8 * s2;
                float2 up = upk(acc2[t][s2]);
                out[r * 32 + ky] = make_float2(up.x, up.y);
            }
        }
    }
}

// ======================= K4: stage3 channel mix per mode — R3 proven =======================
__global__ void __launch_bounds__(128) k_s3() {
    __shared__ float2 Ws[4096];
    __shared__ float2 Ms[1024];
    int m = blockIdx.x;
    {
        const float2* wsrc = (const float2*)g_W + (size_t)m * 4096;
        for (int idx = threadIdx.x; idx < 4096; idx += 128) Ws[idx] = wsrc[idx];
        const float2* msrc = (const float2*)g_M1;
        for (int idx = threadIdx.x; idx < 1024; idx += 128)
            Ms[idx] = msrc[(size_t)idx * NMODE + m];
    }
    __syncthreads();
    int o2 = threadIdx.x & 31, bg = threadIdx.x >> 5;
    u64t acc2[2][4];
    #pragma unroll
    for (int oo = 0; oo < 2; oo++)
        #pragma unroll
        for (int t = 0; t < 4; t++) acc2[oo][t] = 0ULL;
    for (int ii = 0; ii < 64; ii++) {
        float2 wa = Ws[ii * 64 + 2 * o2];
        float2 wb = Ws[ii * 64 + 2 * o2 + 1];
        u64t waP = pk(wa.x, wa.y), waN = pk(-wa.y, wa.x);
        u64t wbP = pk(wb.x, wb.y), wbN = pk(-wb.y, wb.x);
        #pragma unroll
        for (int t = 0; t < 4; t++) {
            float2 mm = Ms[(bg + 4 * t) * 64 + ii];
            u64t mdx = pk2(mm.x), mdy = pk2(mm.y);
            fma2(acc2[0][t], mdx, waP); fma2(acc2[0][t], mdy, waN);
            fma2(acc2[1][t], mdx, wbP); fma2(acc2[1][t], mdy, wbN);
        }
    }
    float2* out = (float2*)g_M2 + (size_t)m * 1024;
    #pragma unroll
    for (int t = 0; t < 4; t++)
        #pragma unroll
        for (int oo = 0; oo < 2; oo++) {
            float2 up = upk(acc2[oo][t]);
            out[(bg + 4 * t) * 64 + 2 * o2 + oo] = make_float2(up.x, up.y);
        }
}

// ======================= K5: stage4 inverse row DFT (R3 math, ky split across 2 blocks) =======================
// P[bo][s][ky] = sum_r M2[r*32+ky][bo] * e^{+2pi i (r-31) s/256}
__global__ void __launch_bounds__(512) k_s4() {
    __shared__ float2 Ms[63 * 16];
    __shared__ u64t ccT[256], nspsT[256];
    int bo = blockIdx.x, kh = blockIdx.y;   // kh: which 16-ky half
    if (threadIdx.x < 256) {
        int idx = threadIdx.x;
        ccT[idx] = g_cc[idx];
        nspsT[idx] = g_nsps[idx];
    }
    {
        const float2* msrc = (const float2*)g_M2;
        for (int idx = threadIdx.x; idx < 63 * 16; idx += 512) {
            int r = idx >> 4, kyl = idx & 15;
            Ms[idx] = msrc[(size_t)(r * 32 + kh * 16 + kyl) * 1024 + bo];
        }
    }
    __syncthreads();
    int kyg = threadIdx.x & 7, sg = threadIdx.x >> 3;  // 8 x 64
    u64t acc2[4][2];   // {pR, pI} — 4 s tiles x 2 ky tiles
    #pragma unroll
    for (int t = 0; t < 4; t++)
        #pragma unroll
        for (int u = 0; u < 2; u++) acc2[t][u] = 0ULL;

    for (int r = 0; r < 63; r++) {
        int fx = r - 31;
        u64t m2[2], msw[2], c2[4], sp[4];
        #pragma unroll
        for (int u = 0; u < 2; u++) {
            m2[u] = *(const u64t*)&Ms[r * 16 + kyg + 8 * u];
            float2 f = upk(m2[u]);
            msw[u] = pk(f.y, f.x);         // {mi, mr}
        }
        #pragma unroll
        for (int t = 0; t < 4; t++) {
            int s2 = sg + 64 * t;
            int idx = (fx * s2) & 255;
            c2[t] = ccT[idx];
            sp[t] = nspsT[idx];            // {-sn, sn}
        }
        #pragma unroll
        for (int t = 0; t < 4; t++)
            #pragma unroll
            for (int u = 0; u < 2; u++) {
                fma2(acc2[t][u], c2[t], m2[u]);   // pR+=c*mr,  pI+=c*mi
                fma2(acc2[t][u], sp[t], msw[u]);  // pR-=sn*mi, pI+=sn*mr
            }
    }
    float2* out = (float2*)(g_TP + (size_t)bo * SS * KKC);  // reuse T buffer as P
    #pragma unroll
    for (int t = 0; t < 4; t++)
        #pragma unroll
        for (int u = 0; u < 2; u++) {
            float2 up = upk(acc2[t][u]);
            out[(sg + 64 * t) * 32 + kh * 16 + kyg + 8 * u] = make_float2(up.x, up.y);
        }
}

// ======================= K6: stage5 inverse column (GEMM 262144x256x64) — R3 proven =======================
__global__ void __launch_bounds__(256) k_s5(float* __restrict__ y) {
    extern __shared__ float sm[];
    float* As = sm;                  // [64][65]
    float* Bs = sm + 64 * 65;        // [64][256]
    for (int idx = threadIdx.x; idx < 64 * 256; idx += 256) {
        int kk = idx >> 8, t = idx & 255, ky = kk >> 1;
        int a = (ky * t) & 255;
        Bs[idx] = (kk & 1) ? -g_tab[256 + a] : g_tab[a];
    }
    int row0 = blockIdx.x * 64;
    {
        const float4* src = (const float4*)(g_TP + (size_t)row0 * 64);
        for (int f = threadIdx.x; f < 1024; f += 256) {
            float4 v4 = src[f];
            int r = f >> 4, c4 = (f & 15) * 4;
            As[(c4 + 0) * 65 + r] = v4.x;
            As[(c4 + 1) * 65 + r] = v4.y;
            As[(c4 + 2) * 65 + r] = v4.z;
            As[(c4 + 3) * 65 + r] = v4.w;
        }
    }
    __syncthreads();
    int i = threadIdx.x & 15, j = threadIdx.x >> 4;
    u64t acc2[4][8];
    #pragma unroll
    for (int t = 0; t < 4; t++)
        #pragma unroll
        for (int p = 0; p < 8; p++) acc2[t][p] = 0ULL;
    #pragma unroll 2
    for (int k = 0; k < 64; k++) {
        u64t a2[4], b2[8];
        #pragma unroll
        for (int t = 0; t < 4; t++) a2[t] = pk2(As[k * 65 + i + 16 * t]);
        #pragma unroll
        for (int p = 0; p < 8; p++)
            b2[p] = *(const u64t*)&Bs[k * 256 + 2 * (j + 16 * p)];
        #pragma unroll
        for (int t = 0; t < 4; t++)
            #pragma unroll
            for (int p = 0; p < 8; p++) fma2(acc2[t][p], a2[t], b2[p]);
    }
    __syncthreads();
    float* sC = sm;  // [64][257]
    #pragma unroll
    for (int t = 0; t < 4; t++)
        #pragma unroll
        for (int p = 0; p < 8; p++) {
            float2 up = upk(acc2[t][p]);
            int c = 2 * (j + 16 * p);
            sC[(i + 16 * t) * 257 + c]     = up.x;
            sC[(i + 16 * t) * 257 + c + 1] = up.y;
        }
    __syncthreads();
    for (int f = threadIdx.x; f < 64 * 64; f += 256) {
        int r = f >> 6, c4 = (f & 63) * 4;
        float4 v4 = make_float4(sC[r * 257 + c4], sC[r * 257 + c4 + 1],
                                sC[r * 257 + c4 + 2], sC[r * 257 + c4 + 3]);
        ((float4*)(y + (size_t)(row0 + r) * 256))[f & 63] = v4;
    }
}

// ======================= launcher =======================
extern "C" void kernel_launch(void* const* d_in, const int* in_sizes, int n_in,
                              void* d_out, int out_size) {
    const float* x   = (const float*)d_in[0];
    const float* y0r = (const float*)d_in[1];
    const float* y0i = (const float*)d_in[2];
    const float* ypr = (const float*)d_in[3];
    const float* ypi = (const float*)d_in[4];
    const float* w00 = (const float*)d_in[5];
    float* y = (float*)d_out;

    const int smem_s1 = (32 * 257 + 256 * 64) * 4;
    const int smem_s2 = 256 * 64 * 4;                // Ts only; trig tables are static
    const int smem_s5 = (64 * 65 + 64 * 256) * 4;

    cudaFuncSetAttribute(k_s1, cudaFuncAttributeMaxDynamicSharedMemorySize, smem_s1);
    cudaFuncSetAttribute(k_s2, cudaFuncAttributeMaxDynamicSharedMemorySize, smem_s2);
    cudaFuncSetAttribute(k_s5, cudaFuncAttributeMaxDynamicSharedMemorySize, smem_s5);

    k_tab<<<1, 256>>>();
    k_wbuild<<<dim3(63, 128), dim3(32, 8)>>>(y0r, y0i, ypr, ypi, w00);
    k_s1<<<1024, 256, smem_s1>>>(x);
    k_s2<<<1024, 256, smem_s2>>>();
    k_s3<<<2016, 128>>>();
    k_s4<<<dim3(1024, 2), 512>>>();
    k_s5<<<4096, 256, smem_s5>>>(y);
}

// round 14
// speedup vs baseline: 1.2455x; 1.2455x over previous
#include <cuda_runtime.h>
#include <math.h>

// Problem constants
#define BB   16
#define CI   64
#define CO   64
#define SS   256
#define MM1  32
#define MM2  32
#define NR   63            // 2*m1-1 fx modes (fx = r-31)
#define NMODE (NR*MM2)     // 2016
#define NBI  (BB*CI)       // 1024
#define NBO  (BB*CO)       // 1024
#define KKC  64            // 2*MM2 interleaved re/im columns

typedef unsigned long long u64t;

// ---- packed f32x2 helpers (FFMA2 path, Blackwell-only via PTX) ----
__device__ __forceinline__ u64t pk(float lo, float hi) {
    u64t r;
    asm("mov.b64 %0, {%1, %2};" : "=l"(r)
        : "r"(__float_as_uint(lo)), "r"(__float_as_uint(hi)));
    return r;
}
__device__ __forceinline__ u64t pk2(float v) { return pk(v, v); }
__device__ __forceinline__ float2 upk(u64t v) {
    unsigned lo, hi;
    asm("mov.b64 {%0, %1}, %2;" : "=r"(lo), "=r"(hi) : "l"(v));
    return make_float2(__uint_as_float(lo), __uint_as_float(hi));
}
__device__ __forceinline__ void fma2(u64t& d, u64t a, u64t b) {
    asm("fma.rn.f32x2 %0, %1, %2, %3;" : "=l"(d) : "l"(a), "l"(b), "l"(d));
}

// -------- device scratch --------
__device__ __align__(16) float g_tab[512];                    // cos[0..255], sin[256..511]
__device__ __align__(16) u64t  g_cc[256];                     // {c,c}
__device__ __align__(16) u64t  g_ss[256];                     // {s,s}
__device__ __align__(16) float g_TP[(size_t)NBI * SS * KKC];  // stage1 out T, reused as stage4 out P
__device__ __align__(16) float g_M1[(size_t)NBI * NMODE * 2]; // [bi][mode][2]
__device__ __align__(16) float g_W [(size_t)NMODE * CI * CO * 2]; // [mode][i*64+o][2] (scaled)
__device__ __align__(16) float g_M2[(size_t)NMODE * NBO * 2]; // [mode][b*64+o][2]

// ======================= K0: trig table =======================
__global__ void k_tab() {
    int n = threadIdx.x;
    double a = 2.0 * M_PI * (double)n / 256.0;
    float c = (float)cos(a), s = (float)sin(a);
    g_tab[n]       = c;
    g_tab[256 + n] = s;
    g_cc[n] = pk2(c);
    g_ss[n] = pk2(s);
}

// ======================= K1: weight build + transpose =======================
__global__ void k_wbuild(const float* __restrict__ y0r, const float* __restrict__ y0i,
                         const float* __restrict__ ypr, const float* __restrict__ ypi,
                         const float* __restrict__ w00) {
    __shared__ float2 tile[32][33];
    int m0 = blockIdx.x * 32, io0 = blockIdx.y * 32;
    int tx = threadIdx.x, ty = threadIdx.y;   // 32 x 8
    #pragma unroll
    for (int q = 0; q < 4; q++) {
        int io = io0 + ty + 8 * q;
        int m  = m0 + tx;
        int r = m >> 5, k = m & 31;
        float wr, wi;
        if (k == 0) {
            if (r < 31)       { wr = y0r[io * 31 + r];        wi =  y0i[io * 31 + r]; }
            else if (r == 31) { wr = w00[io];                 wi =  0.f; }
            else              { wr = y0r[io * 31 + (62 - r)]; wi = -y0i[io * 31 + (62 - r)]; }
        } else {
            int idx = (io * 63 + r) * 31 + (k - 1);
            wr = ypr[idx]; wi = ypi[idx];
        }
        float sc = (k == 0 ? 1.0f : 2.0f) * (1.0f / 65536.0f);
        tile[ty + 8 * q][tx] = make_float2(wr * sc, wi * sc);
    }
    __syncthreads();
    #pragma unroll
    for (int q = 0; q < 4; q++) {
        int m  = m0 + ty + 8 * q;
        int io = io0 + tx;
        float2 w = tile[tx][ty + 8 * q];
        ((float2*)g_W)[(size_t)m * 4096 + io] = w;
    }
}

// ======================= K2: stage1 column DFT (GEMM 262144x64x256) — R3 proven =======================
__global__ void __launch_bounds__(256) k_s1(const float* __restrict__ x) {
    extern __shared__ float sm[];
    float* As = sm;                 // [32][257] transposed A tile
    float* Es = sm + 32 * 257;      // [256][64]
    for (int idx = threadIdx.x; idx < 256 * 64; idx += 256) {
        int v = idx >> 6, kk = idx & 63, ky = kk >> 1;
        int a = (ky * v) & 255;
        Es[idx] = (kk & 1) ? -g_tab[256 + a] : g_tab[a];
    }
    int row0 = blockIdx.x * 256;
    int i = threadIdx.x & 31, j = threadIdx.x >> 5;
    u64t acc2[8][4];
    #pragma unroll
    for (int t = 0; t < 8; t++)
        #pragma unroll
        for (int p = 0; p < 4; p++) acc2[t][p] = 0ULL;

    for (int k0 = 0; k0 < 256; k0 += 32) {
        __syncthreads();
        const float4* src = (const float4*)(x + (size_t)(row0 + threadIdx.x) * 256 + k0);
        #pragma unroll
        for (int q = 0; q < 8; q++) {
            float4 v4 = src[q];
            As[(q * 4 + 0) * 257 + threadIdx.x] = v4.x;
            As[(q * 4 + 1) * 257 + threadIdx.x] = v4.y;
            As[(q * 4 + 2) * 257 + threadIdx.x] = v4.z;
            As[(q * 4 + 3) * 257 + threadIdx.x] = v4.w;
        }
        __syncthreads();
        #pragma unroll 4
        for (int k = 0; k < 32; k++) {
            u64t a2[8], b2[4];
            #pragma unroll
            for (int t = 0; t < 8; t++) a2[t] = pk2(As[k * 257 + i + 32 * t]);
            #pragma unroll
            for (int p = 0; p < 4; p++)
                b2[p] = *(const u64t*)&Es[(k0 + k) * 64 + 2 * (j + 8 * p)];
            #pragma unroll
            for (int t = 0; t < 8; t++)
                #pragma unroll
                for (int p = 0; p < 4; p++) fma2(acc2[t][p], a2[t], b2[p]);
        }
    }
    __syncthreads();
    float* sC = sm;  // [256][65]
    #pragma unroll
    for (int t = 0; t < 8; t++)
        #pragma unroll
        for (int p = 0; p < 4; p++) {
            float2 up = upk(acc2[t][p]);
            int c = 2 * (j + 8 * p);
            sC[(i + 32 * t) * 65 + c]     = up.x;
            sC[(i + 32 * t) * 65 + c + 1] = up.y;
        }
    __syncthreads();
    for (int f = threadIdx.x; f < 256 * 16; f += 256) {
        int r = f >> 4, c4 = (f & 15) * 4;
        float4 v4 = make_float4(sC[r * 65 + c4], sC[r * 65 + c4 + 1],
                                sC[r * 65 + c4 + 2], sC[r * 65 + c4 + 3]);
        ((float4*)(g_TP + (size_t)(row0 + r) * 64))[f & 15] = v4;
    }
}

// ======================= K3: stage2 row DFT per image — symmetric fold =======================
// For d = fx >= 0:  S = sum_u {tr,ti}*cos(d u),  T = sum_u {tr,ti}*sin(d u)
// out(r=31+d) = (S.x+T.y, S.y-T.x);  out(r=31-d) = (S.x-T.y, S.y+T.x)
__global__ void __launch_bounds__(128) k_s2() {
    extern __shared__ float sm[];
    float* Ts = sm;            // [256][64] interleaved re/im
    float* st = sm + 256 * 64; // [512] trig
    int bi = blockIdx.x;
    for (int idx = threadIdx.x; idx < 512; idx += 128) st[idx] = g_tab[idx];
    {
        const float4* src = (const float4*)(g_TP + (size_t)bi * SS * KKC);
        for (int idx = threadIdx.x; idx < 256 * 16; idx += 128)
            ((float4*)Ts)[idx] = src[idx];
    }
    __syncthreads();
    int fxg = threadIdx.x & 15, kyg = threadIdx.x >> 4;  // 16 x 8
    u64t accS[2][4], accT[2][4];
    #pragma unroll
    for (int t = 0; t < 2; t++)
        #pragma unroll
        for (int s2 = 0; s2 < 4; s2++) { accS[t][s2] = 0ULL; accT[t][s2] = 0ULL; }

    #pragma unroll 2
    for (int u = 0; u < 256; u++) {
        u64t tv[4], c2[2], s2v[2];
        #pragma unroll
        for (int s2 = 0; s2 < 4; s2++)
            tv[s2] = *(const u64t*)&Ts[(u * 32 + kyg + 8 * s2) * 2];
        #pragma unroll
        for (int t = 0; t < 2; t++) {
            int d = fxg + 16 * t;
            int idx = (d * u) & 255;
            c2[t]  = pk2(st[idx]);
            s2v[t] = pk2(st[256 + idx]);
        }
        #pragma unroll
        for (int t = 0; t < 2; t++)
            #pragma unroll
            for (int s2 = 0; s2 < 4; s2++) {
                fma2(accS[t][s2], tv[s2], c2[t]);
                fma2(accT[t][s2], tv[s2], s2v[t]);
            }
    }
    float2* out = (float2*)(g_M1 + (size_t)bi * NMODE * 2);
    #pragma unroll
    for (int t = 0; t < 2; t++) {
        int d = fxg + 16 * t;
        #pragma unroll
        for (int s2 = 0; s2 < 4; s2++) {
            int ky = kyg + 8 * s2;
            float2 S = upk(accS[t][s2]), T = upk(accT[t][s2]);
            out[(31 + d) * 32 + ky] = make_float2(S.x + T.y, S.y - T.x);
            if (d > 0)
                out[(31 - d) * 32 + ky] = make_float2(S.x - T.y, S.y + T.x);
        }
    }
}

// ======================= K4: stage3 channel mix per mode — R3 proven =======================
__global__ void __launch_bounds__(128) k_s3() {
    __shared__ float2 Ws[4096];
    __shared__ float2 Ms[1024];
    int m = blockIdx.x;
    {
        const float2* wsrc = (const float2*)g_W + (size_t)m * 4096;
        for (int idx = threadIdx.x; idx < 4096; idx += 128) Ws[idx] = wsrc[idx];
        const float2* msrc = (const float2*)g_M1;
        for (int idx = threadIdx.x; idx < 1024; idx += 128)
            Ms[idx] = msrc[(size_t)idx * NMODE + m];
    }
    __syncthreads();
    int o2 = threadIdx.x & 31, bg = threadIdx.x >> 5;
    u64t acc2[2][4];
    #pragma unroll
    for (int oo = 0; oo < 2; oo++)
        #pragma unroll
        for (int t = 0; t < 4; t++) acc2[oo][t] = 0ULL;
    for (int ii = 0; ii < 64; ii++) {
        float2 wa = Ws[ii * 64 + 2 * o2];
        float2 wb = Ws[ii * 64 + 2 * o2 + 1];
        u64t waP = pk(wa.x, wa.y), waN = pk(-wa.y, wa.x);
        u64t wbP = pk(wb.x, wb.y), wbN = pk(-wb.y, wb.x);
        #pragma unroll
        for (int t = 0; t < 4; t++) {
            float2 mm = Ms[(bg + 4 * t) * 64 + ii];
            u64t mdx = pk2(mm.x), mdy = pk2(mm.y);
            fma2(acc2[0][t], mdx, waP); fma2(acc2[0][t], mdy, waN);
            fma2(acc2[1][t], mdx, wbP); fma2(acc2[1][t], mdy, wbN);
        }
    }
    float2* out = (float2*)g_M2 + (size_t)m * 1024;
    #pragma unroll
    for (int t = 0; t < 4; t++)
        #pragma unroll
        for (int oo = 0; oo < 2; oo++) {
            float2 up = upk(acc2[oo][t]);
            out[(bg + 4 * t) * 64 + 2 * o2 + oo] = make_float2(up.x, up.y);
        }
}

// ======================= K5: stage4 inverse row DFT — symmetric fold =======================
// A = M(31+d)+M(31-d), B = M(31+d)-M(31-d)  (d=0: A=M31, B=0)
// P(s) += {c,c}*{Ar,Ai} + {s,s}*{-Bi,Br},  c=cos(2pi d s/256), s=sin(...)
__global__ void __launch_bounds__(512) k_s4() {
    __shared__ u64t Asm[32 * 32];     // {Ar, Ai}
    __shared__ u64t Bsm[32 * 32];     // {-Bi, Br}
    __shared__ u64t ccT[256], ssT[256];
    int bo = blockIdx.x;
    if (threadIdx.x < 256) {
        int idx = threadIdx.x;
        ccT[idx] = g_cc[idx];
        ssT[idx] = g_ss[idx];
    }
    {
        const float2* msrc = (const float2*)g_M2;
        for (int idx = threadIdx.x; idx < 1024; idx += 512) {
            int d = idx >> 5, ky = idx & 31;
            float2 Mp = msrc[(size_t)((31 + d) * 32 + ky) * 1024 + bo];
            float Ar, Ai, nBi, Br;
            if (d == 0) {
                Ar = Mp.x; Ai = Mp.y; nBi = 0.f; Br = 0.f;
            } else {
                float2 Mm = msrc[(size_t)((31 - d) * 32 + ky) * 1024 + bo];
                Ar = Mp.x + Mm.x;  Ai = Mp.y + Mm.y;
                Br = Mp.x - Mm.x;  nBi = -(Mp.y - Mm.y);
            }
            Asm[idx] = pk(Ar, Ai);
            Bsm[idx] = pk(nBi, Br);
        }
    }
    __syncthreads();
    int kyg = threadIdx.x & 7, sg = threadIdx.x >> 3;  // 8 x 64
    u64t acc2[4][4];   // {pR, pI} — 4 s tiles x 4 ky pairs
    #pragma unroll
    for (int t = 0; t < 4; t++)
        #pragma unroll
        for (int u = 0; u < 4; u++) acc2[t][u] = 0ULL;

    for (int d = 0; d < 32; d++) {
        u64t a2[4], b2[4], c2[4], s2[4];
        #pragma unroll
        for (int u = 0; u < 4; u++) {
            a2[u] = Asm[d * 32 + kyg + 8 * u];
            b2[u] = Bsm[d * 32 + kyg + 8 * u];
        }
        #pragma unroll
        for (int t = 0; t < 4; t++) {
            int s = sg + 64 * t;
            int idx = (d * s) & 255;
            c2[t] = ccT[idx];
            s2[t] = ssT[idx];
        }
        #pragma unroll
        for (int t = 0; t < 4; t++)
            #pragma unroll
            for (int u = 0; u < 4; u++) {
                fma2(acc2[t][u], c2[t], a2[u]);   // pR+=c*Ar,   pI+=c*Ai
                fma2(acc2[t][u], s2[t], b2[u]);   // pR+=-s*Bi,  pI+=s*Br
            }
    }
    float2* out = (float2*)(g_TP + (size_t)bo * SS * KKC);  // reuse T buffer as P
    #pragma unroll
    for (int t = 0; t < 4; t++)
        #pragma unroll
        for (int u = 0; u < 4; u++) {
            float2 up = upk(acc2[t][u]);
            out[(sg + 64 * t) * 32 + kyg + 8 * u] = make_float2(up.x, up.y);
        }
}

// ======================= K6: stage5 inverse column (GEMM 262144x256x64) — R3 proven =======================
__global__ void __launch_bounds__(256) k_s5(float* __restrict__ y) {
    extern __shared__ float sm[];
    float* As = sm;                  // [64][65]
    float* Bs = sm + 64 * 65;        // [64][256]
    for (int idx = threadIdx.x; idx < 64 * 256; idx += 256) {
        int kk = idx >> 8, t = idx & 255, ky = kk >> 1;
        int a = (ky * t) & 255;
        Bs[idx] = (kk & 1) ? -g_tab[256 + a] : g_tab[a];
    }
    int row0 = blockIdx.x * 64;
    {
        const float4* src = (const float4*)(g_TP + (size_t)row0 * 64);
        for (int f = threadIdx.x; f < 1024; f += 256) {
            float4 v4 = src[f];
            int r = f >> 4, c4 = (f & 15) * 4;
            As[(c4 + 0) * 65 + r] = v4.x;
            As[(c4 + 1) * 65 + r] = v4.y;
            As[(c4 + 2) * 65 + r] = v4.z;
            As[(c4 + 3) * 65 + r] = v4.w;
        }
    }
    __syncthreads();
    int i = threadIdx.x & 15, j = threadIdx.x >> 4;
    u64t acc2[4][8];
    #pragma unroll
    for (int t = 0; t < 4; t++)
        #pragma unroll
        for (int p = 0; p < 8; p++) acc2[t][p] = 0ULL;
    #pragma unroll 2
    for (int k = 0; k < 64; k++) {
        u64t a2[4], b2[8];
        #pragma unroll
        for (int t = 0; t < 4; t++) a2[t] = pk2(As[k * 65 + i + 16 * t]);
        #pragma unroll
        for (int p = 0; p < 8; p++)
            b2[p] = *(const u64t*)&Bs[k * 256 + 2 * (j + 16 * p)];
        #pragma unroll
        for (int t = 0; t < 4; t++)
            #pragma unroll
            for (int p = 0; p < 8; p++) fma2(acc2[t][p], a2[t], b2[p]);
    }
    __syncthreads();
    float* sC = sm;  // [64][257]
    #pragma unroll
    for (int t = 0; t < 4; t++)
        #pragma unroll
        for (int p = 0; p < 8; p++) {
            float2 up = upk(acc2[t][p]);
            int c = 2 * (j + 16 * p);
            sC[(i + 16 * t) * 257 + c]     = up.x;
            sC[(i + 16 * t) * 257 + c + 1] = up.y;
        }
    __syncthreads();
    for (int f = threadIdx.x; f < 64 * 64; f += 256) {
        int r = f >> 6, c4 = (f & 63) * 4;
        float4 v4 = make_float4(sC[r * 257 + c4], sC[r * 257 + c4 + 1],
                                sC[r * 257 + c4 + 2], sC[r * 257 + c4 + 3]);
        ((float4*)(y + (size_t)(row0 + r) * 256))[f & 63] = v4;
    }
}

// ======================= launcher =======================
extern "C" void kernel_launch(void* const* d_in, const int* in_sizes, int n_in,
                              void* d_out, int out_size) {
    const float* x   = (const float*)d_in[0];
    const float* y0r = (const float*)d_in[1];
    const float* y0i = (const float*)d_in[2];
    const float* ypr = (const float*)d_in[3];
    const float* ypi = (const float*)d_in[4];
    const float* w00 = (const float*)d_in[5];
    float* y = (float*)d_out;

    const int smem_s1 = (32 * 257 + 256 * 64) * 4;
    const int smem_s2 = (256 * 64 + 512) * 4;
    const int smem_s5 = (64 * 65 + 64 * 256) * 4;

    cudaFuncSetAttribute(k_s1, cudaFuncAttributeMaxDynamicSharedMemorySize, smem_s1);
    cudaFuncSetAttribute(k_s2, cudaFuncAttributeMaxDynamicSharedMemorySize, smem_s2);
    cudaFuncSetAttribute(k_s5, cudaFuncAttributeMaxDynamicSharedMemorySize, smem_s5);

    k_tab<<<1, 256>>>();
    k_wbuild<<<dim3(63, 128), dim3(32, 8)>>>(y0r, y0i, ypr, ypi, w00);
    k_s1<<<1024, 256, smem_s1>>>(x);
    k_s2<<<1024, 128, smem_s2>>>();
    k_s3<<<2016, 128>>>();
    k_s4<<<1024, 512>>>();
    k_s5<<<4096, 256, smem_s5>>>(y);
}

// round 16
// speedup vs baseline: 1.4086x; 1.1310x over previous
#include <cuda_runtime.h>
#include <math.h>

// Problem constants
#define BB   16
#define CI   64
#define CO   64
#define SS   256
#define MM1  32
#define MM2  32
#define NR   63            // 2*m1-1 fx modes (fx = r-31)
#define NMODE (NR*MM2)     // 2016
#define NBI  (BB*CI)       // 1024
#define NBO  (BB*CO)       // 1024
#define KKC  64            // 2*MM2 interleaved re/im columns

typedef unsigned long long u64t;

// ---- packed f32x2 helpers (FFMA2 path, Blackwell-only via PTX) ----
__device__ __forceinline__ u64t pk(float lo, float hi) {
    u64t r;
    asm("mov.b64 %0, {%1, %2};" : "=l"(r)
        : "r"(__float_as_uint(lo)), "r"(__float_as_uint(hi)));
    return r;
}
__device__ __forceinline__ u64t pk2(float v) { return pk(v, v); }
__device__ __forceinline__ float2 upk(u64t v) {
    unsigned lo, hi;
    asm("mov.b64 {%0, %1}, %2;" : "=r"(lo), "=r"(hi) : "l"(v));
    return make_float2(__uint_as_float(lo), __uint_as_float(hi));
}
__device__ __forceinline__ void fma2(u64t& d, u64t a, u64t b) {
    asm("fma.rn.f32x2 %0, %1, %2, %3;" : "=l"(d) : "l"(a), "l"(b), "l"(d));
}

// -------- device scratch --------
__device__ __align__(16) float g_tab[512];                    // cos[0..255], sin[256..511]
__device__ __align__(16) u64t  g_cc[256];                     // {c,c}
__device__ __align__(16) u64t  g_ss[256];                     // {s,s}
__device__ __align__(16) float g_TP[(size_t)NBI * SS * KKC];  // stage1 out T, reused as stage4 out P
__device__ __align__(16) float g_M1[(size_t)NBI * NMODE * 2]; // [bi][mode][2]
__device__ __align__(16) float g_W [(size_t)NMODE * CI * CO * 2]; // [mode][i*64+o][2] (scaled)
__device__ __align__(16) float g_M2[(size_t)NMODE * NBO * 2]; // [mode][b*64+o][2]

// ======================= K0: trig table =======================
__global__ void k_tab() {
    int n = threadIdx.x;
    double a = 2.0 * M_PI * (double)n / 256.0;
    float c = (float)cos(a), s = (float)sin(a);
    g_tab[n]       = c;
    g_tab[256 + n] = s;
    g_cc[n] = pk2(c);
    g_ss[n] = pk2(s);
}

// ======================= K1: weight build + transpose =======================
__global__ void k_wbuild(const float* __restrict__ y0r, const float* __restrict__ y0i,
                         const float* __restrict__ ypr, const float* __restrict__ ypi,
                         const float* __restrict__ w00) {
    __shared__ float2 tile[32][33];
    int m0 = blockIdx.x * 32, io0 = blockIdx.y * 32;
    int tx = threadIdx.x, ty = threadIdx.y;   // 32 x 8
    #pragma unroll
    for (int q = 0; q < 4; q++) {
        int io = io0 + ty + 8 * q;
        int m  = m0 + tx;
        int r = m >> 5, k = m & 31;
        float wr, wi;
        if (k == 0) {
            if (r < 31)       { wr = y0r[io * 31 + r];        wi =  y0i[io * 31 + r]; }
            else if (r == 31) { wr = w00[io];                 wi =  0.f; }
            else              { wr = y0r[io * 31 + (62 - r)]; wi = -y0i[io * 31 + (62 - r)]; }
        } else {
            int idx = (io * 63 + r) * 31 + (k - 1);
            wr = ypr[idx]; wi = ypi[idx];
        }
        float sc = (k == 0 ? 1.0f : 2.0f) * (1.0f / 65536.0f);
        tile[ty + 8 * q][tx] = make_float2(wr * sc, wi * sc);
    }
    __syncthreads();
    #pragma unroll
    for (int q = 0; q < 4; q++) {
        int m  = m0 + ty + 8 * q;
        int io = io0 + tx;
        float2 w = tile[tx][ty + 8 * q];
        ((float2*)g_W)[(size_t)m * 4096 + io] = w;
    }
}

// ======================= K2: stage1 column DFT — symmetric fold (K 256->128) =======================
// e[v]=x[v]+x[256-v], o[v]=x[v]-x[256-v] (v=1..127); e[0]=x[0], o[0]=0
// T[2ky]   = sum_v e[v] cos(ky v) + x[128]*(-1)^ky
// T[2ky+1] = sum_v o[v] * (-sin(ky v))
__global__ void __launch_bounds__(256) k_s1(const float* __restrict__ x) {
    extern __shared__ float smf[];
    u64t* As64 = (u64t*)smf;                 // [32 k][257 rows] {e,o}
    u64t* Es64 = As64 + 32 * 257;            // [128 k][32 ky] {cos, -sin}
    float* x128s = (float*)(Es64 + 128 * 32);  // [256]
    for (int idx = threadIdx.x; idx < 128 * 32; idx += 256) {
        int k = idx >> 5, ky = idx & 31;
        int a = (ky * k) & 255;
        Es64[idx] = pk(g_tab[a], -g_tab[256 + a]);
    }
    int row0 = blockIdx.x * 256;
    const float* xr = x + (size_t)(row0 + threadIdx.x) * 256;
    x128s[threadIdx.x] = xr[128];
    int i = threadIdx.x & 31, j = threadIdx.x >> 5;
    u64t acc2[8][4];
    #pragma unroll
    for (int t = 0; t < 8; t++)
        #pragma unroll
        for (int p = 0; p < 4; p++) acc2[t][p] = 0ULL;

    for (int k0 = 0; k0 < 128; k0 += 32) {
        __syncthreads();
        {
            float carry = (k0 > 0) ? xr[256 - k0] : 0.f;   // mirror of m=0
            #pragma unroll
            for (int q = 0; q < 8; q++) {
                float4 f4 = *(const float4*)(xr + k0 + 4 * q);
                float4 b4 = *(const float4*)(xr + 252 - k0 - 4 * q);
                float m0v = carry, m1v = b4.w, m2v = b4.z, m3v = b4.y;
                carry = b4.x;   // mirror of m=4q+4
                float e0, o0;
                if (k0 == 0 && q == 0) { e0 = f4.x; o0 = 0.f; }
                else                    { e0 = f4.x + m0v; o0 = f4.x - m0v; }
                u64t* dst = As64 + (4 * q) * 257 + threadIdx.x;
                dst[0]       = pk(e0, o0);
                dst[257]     = pk(f4.y + m1v, f4.y - m1v);
                dst[2 * 257] = pk(f4.z + m2v, f4.z - m2v);
                dst[3 * 257] = pk(f4.w + m3v, f4.w - m3v);
            }
        }
        __syncthreads();
        #pragma unroll 4
        for (int k = 0; k < 32; k++) {
            u64t a2[8], b2[4];
            #pragma unroll
            for (int t = 0; t < 8; t++) a2[t] = As64[k * 257 + i + 32 * t];
            #pragma unroll
            for (int p = 0; p < 4; p++)
                b2[p] = Es64[(k0 + k) * 32 + j + 8 * p];
            #pragma unroll
            for (int t = 0; t < 8; t++)
                #pragma unroll
                for (int p = 0; p < 4; p++) fma2(acc2[t][p], a2[t], b2[p]);
        }
    }
    __syncthreads();
    float* sC = smf;  // [256][65] overlays As/Es
    #pragma unroll
    for (int t = 0; t < 8; t++) {
        float x128v = x128s[i + 32 * t];
        #pragma unroll
        for (int p = 0; p < 4; p++) {
            int ky = j + 8 * p;
            float2 up = upk(acc2[t][p]);
            float tc = up.x + ((ky & 1) ? -x128v : x128v);
            sC[(i + 32 * t) * 65 + 2 * ky]     = tc;
            sC[(i + 32 * t) * 65 + 2 * ky + 1] = up.y;
        }
    }
    __syncthreads();
    for (int f = threadIdx.x; f < 256 * 16; f += 256) {
        int r = f >> 4, c4 = (f & 15) * 4;
        float4 v4 = make_float4(sC[r * 65 + c4], sC[r * 65 + c4 + 1],
                                sC[r * 65 + c4 + 2], sC[r * 65 + c4 + 3]);
        ((float4*)(g_TP + (size_t)(row0 + r) * 64))[f & 15] = v4;
    }
}

// ======================= K3: stage2 row DFT per image — symmetric fold (R14 proven) =======================
__global__ void __launch_bounds__(128) k_s2() {
    extern __shared__ float sm[];
    float* Ts = sm;            // [256][64] interleaved re/im
    float* st = sm + 256 * 64; // [512] trig
    int bi = blockIdx.x;
    for (int idx = threadIdx.x; idx < 512; idx += 128) st[idx] = g_tab[idx];
    {
        const float4* src = (const float4*)(g_TP + (size_t)bi * SS * KKC);
        for (int idx = threadIdx.x; idx < 256 * 16; idx += 128)
            ((float4*)Ts)[idx] = src[idx];
    }
    __syncthreads();
    int fxg = threadIdx.x & 15, kyg = threadIdx.x >> 4;  // 16 x 8
    u64t accS[2][4], accT[2][4];
    #pragma unroll
    for (int t = 0; t < 2; t++)
        #pragma unroll
        for (int s2 = 0; s2 < 4; s2++) { accS[t][s2] = 0ULL; accT[t][s2] = 0ULL; }

    #pragma unroll 2
    for (int u = 0; u < 256; u++) {
        u64t tv[4], c2[2], s2v[2];
        #pragma unroll
        for (int s2 = 0; s2 < 4; s2++)
            tv[s2] = *(const u64t*)&Ts[(u * 32 + kyg + 8 * s2) * 2];
        #pragma unroll
        for (int t = 0; t < 2; t++) {
            int d = fxg + 16 * t;
            int idx = (d * u) & 255;
            c2[t]  = pk2(st[idx]);
            s2v[t] = pk2(st[256 + idx]);
        }
        #pragma unroll
        for (int t = 0; t < 2; t++)
            #pragma unroll
            for (int s2 = 0; s2 < 4; s2++) {
                fma2(accS[t][s2], tv[s2], c2[t]);
                fma2(accT[t][s2], tv[s2], s2v[t]);
            }
    }
    float2* out = (float2*)(g_M1 + (size_t)bi * NMODE * 2);
    #pragma unroll
    for (int t = 0; t < 2; t++) {
        int d = fxg + 16 * t;
        #pragma unroll
        for (int s2 = 0; s2 < 4; s2++) {
            int ky = kyg + 8 * s2;
            float2 S = upk(accS[t][s2]), T = upk(accT[t][s2]);
            out[(31 + d) * 32 + ky] = make_float2(S.x + T.y, S.y - T.x);
            if (d > 0)
                out[(31 - d) * 32 + ky] = make_float2(S.x - T.y, S.y + T.x);
        }
    }
}

// ======================= K4: stage3 channel mix per mode — R3 proven =======================
__global__ void __launch_bounds__(128) k_s3() {
    __shared__ float2 Ws[4096];
    __shared__ float2 Ms[1024];
    int m = blockIdx.x;
    {
        const float2* wsrc = (const float2*)g_W + (size_t)m * 4096;
        for (int idx = threadIdx.x; idx < 4096; idx += 128) Ws[idx] = wsrc[idx];
        const float2* msrc = (const float2*)g_M1;
        for (int idx = threadIdx.x; idx < 1024; idx += 128)
            Ms[idx] = msrc[(size_t)idx * NMODE + m];
    }
    __syncthreads();
    int o2 = threadIdx.x & 31, bg = threadIdx.x >> 5;
    u64t acc2[2][4];
    #pragma unroll
    for (int oo = 0; oo < 2; oo++)
        #pragma unroll
        for (int t = 0; t < 4; t++) acc2[oo][t] = 0ULL;
    for (int ii = 0; ii < 64; ii++) {
        float2 wa = Ws[ii * 64 + 2 * o2];
        float2 wb = Ws[ii * 64 + 2 * o2 + 1];
        u64t waP = pk(wa.x, wa.y), waN = pk(-wa.y, wa.x);
        u64t wbP = pk(wb.x, wb.y), wbN = pk(-wb.y, wb.x);
        #pragma unroll
        for (int t = 0; t < 4; t++) {
            float2 mm = Ms[(bg + 4 * t) * 64 + ii];
            u64t mdx = pk2(mm.x), mdy = pk2(mm.y);
            fma2(acc2[0][t], mdx, waP); fma2(acc2[0][t], mdy, waN);
            fma2(acc2[1][t], mdx, wbP); fma2(acc2[1][t], mdy, wbN);
        }
    }
    float2* out = (float2*)g_M2 + (size_t)m * 1024;
    #pragma unroll
    for (int t = 0; t < 4; t++)
        #pragma unroll
        for (int oo = 0; oo < 2; oo++) {
            float2 up = upk(acc2[oo][t]);
            out[(bg + 4 * t) * 64 + 2 * o2 + oo] = make_float2(up.x, up.y);
        }
}

// ======================= K5: stage4 inverse row DFT — symmetric fold (R14 proven) =======================
__global__ void __launch_bounds__(512) k_s4() {
    __shared__ u64t Asm[32 * 32];     // {Ar, Ai}
    __shared__ u64t Bsm[32 * 32];     // {-Bi, Br}
    __shared__ u64t ccT[256], ssT[256];
    int bo = blockIdx.x;
    if (threadIdx.x < 256) {
        int idx = threadIdx.x;
        ccT[idx] = g_cc[idx];
        ssT[idx] = g_ss[idx];
    }
    {
        const float2* msrc = (const float2*)g_M2;
        for (int idx = threadIdx.x; idx < 1024; idx += 512) {
            int d = idx >> 5, ky = idx & 31;
            float2 Mp = msrc[(size_t)((31 + d) * 32 + ky) * 1024 + bo];
            float Ar, Ai, nBi, Br;
            if (d == 0) {
                Ar = Mp.x; Ai = Mp.y; nBi = 0.f; Br = 0.f;
            } else {
                float2 Mm = msrc[(size_t)((31 - d) * 32 + ky) * 1024 + bo];
                Ar = Mp.x + Mm.x;  Ai = Mp.y + Mm.y;
                Br = Mp.x - Mm.x;  nBi = -(Mp.y - Mm.y);
            }
            Asm[idx] = pk(Ar, Ai);
            Bsm[idx] = pk(nBi, Br);
        }
    }
    __syncthreads();
    int kyg = threadIdx.x & 7, sg = threadIdx.x >> 3;  // 8 x 64
    u64t acc2[4][4];
    #pragma unroll
    for (int t = 0; t < 4; t++)
        #pragma unroll
        for (int u = 0; u < 4; u++) acc2[t][u] = 0ULL;

    for (int d = 0; d < 32; d++) {
        u64t a2[4], b2[4], c2[4], s2[4];
        #pragma unroll
        for (int u = 0; u < 4; u++) {
            a2[u] = Asm[d * 32 + kyg + 8 * u];
            b2[u] = Bsm[d * 32 + kyg + 8 * u];
        }
        #pragma unroll
        for (int t = 0; t < 4; t++) {
            int s = sg + 64 * t;
            int idx = (d * s) & 255;
            c2[t] = ccT[idx];
            s2[t] = ssT[idx];
        }
        #pragma unroll
        for (int t = 0; t < 4; t++)
            #pragma unroll
            for (int u = 0; u < 4; u++) {
                fma2(acc2[t][u], c2[t], a2[u]);
                fma2(acc2[t][u], s2[t], b2[u]);
            }
    }
    float2* out = (float2*)(g_TP + (size_t)bo * SS * KKC);
    #pragma unroll
    for (int t = 0; t < 4; t++)
        #pragma unroll
        for (int u = 0; u < 4; u++) {
            float2 up = upk(acc2[t][u]);
            out[(sg + 64 * t) * 32 + kyg + 8 * u] = make_float2(up.x, up.y);
        }
}

// ======================= K6: stage5 inverse column — symmetric fold (N 256->129, K 64->32) =======================
// C = sum_ky Pr*cos(ky t'), S = sum_ky Pi*sin(ky t')
// y[t'] = C - S;  y[256-t'] = C + S  (t'=1..127); t'=0,128: single store (S=0)
__global__ void __launch_bounds__(256) k_s5(float* __restrict__ y) {
    extern __shared__ float smf[];
    u64t* Bs64 = (u64t*)smf;            // [144 t'][33] {cos, sin}
    u64t* As64 = Bs64 + 144 * 33;       // [64 rows][33] {Pr, Pi}
    for (int idx = threadIdx.x; idx < 144 * 32; idx += 256) {
        int tp = idx >> 5, ky = idx & 31;
        int a = (ky * tp) & 255;
        Bs64[tp * 33 + ky] = pk(g_tab[a], g_tab[256 + a]);
    }
    int row0 = blockIdx.x * 64;
    {
        const u64t* src = (const u64t*)(g_TP + (size_t)row0 * 64);
        for (int f = threadIdx.x; f < 64 * 32; f += 256) {
            int r = f >> 5, ky = f & 31;
            As64[r * 33 + ky] = src[f];
        }
    }
    __syncthreads();
    int i = threadIdx.x & 15, j = threadIdx.x >> 4;   // 16 row lanes x 16 t' groups
    u64t acc2[4][9];
    #pragma unroll
    for (int t = 0; t < 4; t++)
        #pragma unroll
        for (int p = 0; p < 9; p++) acc2[t][p] = 0ULL;
    #pragma unroll 4
    for (int k = 0; k < 32; k++) {
        u64t a2[4], b2[9];
        #pragma unroll
        for (int t = 0; t < 4; t++) a2[t] = As64[(i + 16 * t) * 33 + k];
        #pragma unroll
        for (int p = 0; p < 9; p++)
            b2[p] = Bs64[(j + 16 * p) * 33 + k];
        #pragma unroll
        for (int t = 0; t < 4; t++)
            #pragma unroll
            for (int p = 0; p < 9; p++) fma2(acc2[t][p], a2[t], b2[p]);
    }
    __syncthreads();
    float* sC = smf;  // [64][257] overlays Bs/As
    #pragma unroll
    for (int t = 0; t < 4; t++)
        #pragma unroll
        for (int p = 0; p < 9; p++) {
            int tp = j + 16 * p;
            float2 up = upk(acc2[t][p]);
            if (tp <= 128)
                sC[(i + 16 * t) * 257 + tp] = up.x - up.y;
            if (tp >= 1 && tp <= 127)
                sC[(i + 16 * t) * 257 + 256 - tp] = up.x + up.y;
        }
    __syncthreads();
    for (int f = threadIdx.x; f < 64 * 64; f += 256) {
        int r = f >> 6, c4 = (f & 63) * 4;
        float4 v4 = make_float4(sC[r * 257 + c4], sC[r * 257 + c4 + 1],
                                sC[r * 257 + c4 + 2], sC[r * 257 + c4 + 3]);
        ((float4*)(y + (size_t)(row0 + r) * 256))[f & 63] = v4;
    }
}

// ======================= launcher =======================
extern "C" void kernel_launch(void* const* d_in, const int* in_sizes, int n_in,
                              void* d_out, int out_size) {
    const float* x   = (const float*)d_in[0];
    const float* y0r = (const float*)d_in[1];
    const float* y0i = (const float*)d_in[2];
    const float* ypr = (const float*)d_in[3];
    const float* ypi = (const float*)d_in[4];
    const float* w00 = (const float*)d_in[5];
    float* y = (float*)d_out;

    const int smem_s1 = 32 * 257 * 8 + 128 * 32 * 8 + 256 * 4;   // 99584
    const int smem_s2 = (256 * 64 + 512) * 4;
    const int smem_s5 = 64 * 257 * 4;                            // 65792 (> Bs+As = 54912)

    cudaFuncSetAttribute(k_s1, cudaFuncAttributeMaxDynamicSharedMemorySize, smem_s1);
    cudaFuncSetAttribute(k_s2, cudaFuncAttributeMaxDynamicSharedMemorySize, smem_s2);
    cudaFuncSetAttribute(k_s5, cudaFuncAttributeMaxDynamicSharedMemorySize, smem_s5);

    k_tab<<<1, 256>>>();
    k_wbuild<<<dim3(63, 128), dim3(32, 8)>>>(y0r, y0i, ypr, ypi, w00);
    k_s1<<<1024, 256, smem_s1>>>(x);
    k_s2<<<1024, 128, smem_s2>>>();
    k_s3<<<2016, 128>>>();
    k_s4<<<1024, 512>>>();
    k_s5<<<4096, 256, smem_s5>>>(y);
}